// round 14
// baseline (speedup 1.0000x reference)
#include <cuda_runtime.h>
#include <cuda_bf16.h>

// GCN 2-layer regression on GB300. N=100000 nodes, E=3.2M edges, d_in=128, h=16.
//
// 3-launch pipeline, bucketed CSR, oct-per-node fp32 gathers:
//   kernel A: warps 0-6 fill CSR buckets; warp 7 computes raw xw = x @ W1.
//             Device-wide handshake: after all CTAs finish, CTAs 0..147
//             apply dis = rsqrt(cnt+1) scaling in-place (fused scale pass).
//   kernel B: h1 = dis*(self+sum nbr) -> relu+b1 -> @W2 -> *dis -> g_xw2
//   kernel C: h2 likewise -> relu+b2 -> .Wl+bl -> out (+ cnt self-reset)
// All sync state (g_done/g_flag/g_obs) and g_cnt are self-resetting so every
// graph replay starts from the same state (device globals start zeroed).

#define MAXN 100000
#define CAP  128            // per-node bucket capacity (Poisson(32) max deg ~65)

__device__ float4 g_xw [MAXN * 4];     // layer-1 features (raw, then dis-scaled)
__device__ float4 g_xw2[MAXN * 4];     // layer-2 dis-scaled features
__device__ float  g_dis[MAXN];         // deg^{-1/2}
__device__ int    g_cnt[MAXN];         // indegree / fill cursors (self-reset)
__device__ int    g_csr[MAXN * CAP];   // bucketed src ids
__device__ int    g_done;              // CTAs finished fill+gemm
__device__ int    g_flag;              // all-done broadcast
__device__ int    g_obs;               // spinner CTAs finished scale

#define FILL_WARPS 7
#define FILL_THR   (FILL_WARPS * 32)   // 224 fill threads per CTA
#define NSPIN      148                 // CTAs that perform the fused scale

// ---------------------------------------------------------------------------
// Process one chunk of 8 edges starting at e0 = c*8.
__device__ __forceinline__ void fill_chunk(const void* __restrict__ ei,
                                           long long E, long long c, int is64) {
    const long long e0 = c * 8;
    int s[8], d[8];
    int n;
    if (e0 + 8 <= E && (E & 1) == 0) {
        n = 8;
        if (is64) {
            const longlong2* sp = (const longlong2*)ei;
            const longlong2* dp = (const longlong2*)((const long long*)ei + E);
#pragma unroll
            for (int k = 0; k < 4; k++) {
                longlong2 a = sp[c * 4 + k];
                s[2 * k] = (int)a.x; s[2 * k + 1] = (int)a.y;
            }
#pragma unroll
            for (int k = 0; k < 4; k++) {
                longlong2 a = dp[c * 4 + k];
                d[2 * k] = (int)a.x; d[2 * k + 1] = (int)a.y;
            }
        } else if ((E & 3) == 0) {
            const int4* sp = (const int4*)ei;
            const int4* dp = (const int4*)((const int*)ei + E);
#pragma unroll
            for (int k = 0; k < 2; k++) {
                int4 a = sp[c * 2 + k];
                s[4 * k] = a.x; s[4 * k + 1] = a.y;
                s[4 * k + 2] = a.z; s[4 * k + 3] = a.w;
            }
#pragma unroll
            for (int k = 0; k < 2; k++) {
                int4 a = dp[c * 2 + k];
                d[4 * k] = a.x; d[4 * k + 1] = a.y;
                d[4 * k + 2] = a.z; d[4 * k + 3] = a.w;
            }
        } else {
            const int* w = (const int*)ei;
#pragma unroll
            for (int k = 0; k < 8; k++) { s[k] = w[e0 + k]; d[k] = w[E + e0 + k]; }
        }
    } else {
        n = (int)(E - e0 < 8 ? E - e0 : 8);
        for (int k = 0; k < n; k++) {
            if (is64) {
                s[k] = (int)((const long long*)ei)[e0 + k];
                d[k] = (int)((const long long*)ei)[E + e0 + k];
            } else {
                s[k] = ((const int*)ei)[e0 + k];
                d[k] = ((const int*)ei)[E + e0 + k];
            }
        }
    }

    int pos[8];
#pragma unroll
    for (int k = 0; k < 8; k++)
        if (k < n) pos[k] = atomicAdd(&g_cnt[d[k]], 1);
#pragma unroll
    for (int k = 0; k < 8; k++)
        if (k < n) g_csr[((size_t)d[k] << 7) + pos[k]] = s[k];
}

// ---------------------------------------------------------------------------
// Kernel A: warps 0-6 fill; warp 7 raw gemm; fused scale by CTAs < NSPIN.
__global__ void __launch_bounds__(256)
fillgemm_kernel(const float* __restrict__ x, const float* __restrict__ W1,
                const void* __restrict__ ei, long long E, int N) {
    __shared__ float ws[128 * 16];   // W1
    __shared__ float xs[4 * 132];    // x tile for the gemm warp (padded)
    __shared__ int   s_is64;

    const int tid = threadIdx.x;
    const int wid = tid >> 5;

    if (tid == 0) {
        // dtype detect: int64 ids < 2^31 -> every odd 32-bit word is 0.
        const int* w = (const int*)ei;
        int az = 1;
        for (int k = 0; k < 64; k++)
            if (w[2 * k + 1] != 0) { az = 0; break; }
        s_is64 = az;
    }
    for (int i = tid; i < 128 * 16; i += 256) ws[i] = W1[i];
    __syncthreads();
    const int is64 = s_is64;

    if (wid < FILL_WARPS) {
        // ------------------- fill: 8 edges per thread ---------------------
        const long long nC = (E + 7) >> 3;
        const long long F  = (long long)gridDim.x * FILL_THR;
        for (long long c = (long long)blockIdx.x * FILL_THR + tid; c < nC; c += F)
            fill_chunk(ei, E, c, is64);
    } else {
        // ------------------- gemm (1 warp): raw xw = x @ W1 ---------------
        const int gtid = tid - FILL_THR;     // 0..31
        for (int tile = blockIdx.x; tile * 4 < N; tile += gridDim.x) {
            const int base = tile * 4;
            const int rows = min(4, N - base);
            const float4* xg = (const float4*)(x + (size_t)base * 128);
#pragma unroll
            for (int u = 0; u < 4; u++) {
                int i = gtid + u * 32;           // 0..127
                if (i < rows * 32) {
                    float4 v = xg[i];
                    int r = i >> 5, cc = (i & 31) * 4;
                    float* p = xs + r * 132 + cc;
                    p[0] = v.x; p[1] = v.y; p[2] = v.z; p[3] = v.w;
                }
            }
            __syncwarp();

            const int node = gtid >> 3;     // 0..3
            const int j0   = gtid & 7;      // cols j0 and j0+8
            if (node < rows) {
                const float* xr = xs + node * 132;
                float a0 = 0.f, a1 = 0.f;
#pragma unroll
                for (int k = 0; k < 128; k++) {
                    float xv = xr[k];
                    a0 = fmaf(xv, ws[k * 16 + j0],     a0);
                    a1 = fmaf(xv, ws[k * 16 + j0 + 8], a1);
                }
                float* xwp = (float*)g_xw + (size_t)(base + node) * 16;
                xwp[j0]     = a0;           // raw; scaled after the handshake
                xwp[j0 + 8] = a1;
            }
            __syncwarp();
        }
    }

    // ---------------- device-wide handshake --------------------------------
    __threadfence();
    __syncthreads();
    if (tid == 0) {
        int old = atomicAdd(&g_done, 1);
        if (old == (int)gridDim.x - 1) atomicExch(&g_flag, 1);
    }

    const int nspin = min((int)gridDim.x, NSPIN);
    if ((int)blockIdx.x >= nspin) return;   // non-spinners retire, freeing slots

    // spin until every CTA has finished fill+gemm
    if ((tid & 31) == 0) {
        while (atomicAdd(&g_flag, 0) == 0) __nanosleep(256);
    }
    __syncwarp();
    __threadfence();

    // ---------------- fused scale: dis + in-place xw *= dis ----------------
    const int total = N * 4;
    for (int i = blockIdx.x * 256 + tid; i < total; i += nspin * 256) {
        int node = i >> 2;
        float dv = rsqrtf((float)(g_cnt[node] + 1));
        float4 v = g_xw[i];
        g_xw[i] = make_float4(v.x * dv, v.y * dv, v.z * dv, v.w * dv);
        if ((i & 3) == 0) g_dis[node] = dv;
    }

    // last spinner CTA resets the sync state for the next replay
    __syncthreads();
    if (tid == 0) {
        int o = atomicAdd(&g_obs, 1);
        if (o == nspin - 1) {
            g_done = 0;
            g_obs  = 0;
            __threadfence();
            g_flag = 0;
        }
    }
}

// ---------------------------------------------------------------------------
// Oct-cooperative neighbor sum. 8 threads per node:
//   column j = lane&3 ; half h = (lane>>2)&1 takes chunks [h*4 + 8i, ..+3].
// One shfl_xor(4) folds the halves. Returns dis*(self+sum) for column j.
__device__ __forceinline__ float4 gather_oct(const float4* __restrict__ feat,
                                             int node, int lane, int cnt) {
    const int j = lane & 3;
    const int h = (lane >> 2) & 1;
    const int beg = node << 7;

    float ax = 0.f, ay = 0.f, az = 0.f, aw = 0.f;

    for (int k = h * 4; k < cnt; k += 8) {
        int4 s4 = *(const int4*)&g_csr[beg + k];   // in-bucket (k 4-aligned < cnt<=128)
        if (k + 0 < cnt) {
            float4 v = __ldg(feat + (size_t)s4.x * 4 + j);
            ax += v.x; ay += v.y; az += v.z; aw += v.w;
        }
        if (k + 1 < cnt) {
            float4 v = __ldg(feat + (size_t)s4.y * 4 + j);
            ax += v.x; ay += v.y; az += v.z; aw += v.w;
        }
        if (k + 2 < cnt) {
            float4 v = __ldg(feat + (size_t)s4.z * 4 + j);
            ax += v.x; ay += v.y; az += v.z; aw += v.w;
        }
        if (k + 3 < cnt) {
            float4 v = __ldg(feat + (size_t)s4.w * 4 + j);
            ax += v.x; ay += v.y; az += v.z; aw += v.w;
        }
    }

    if (h == 0) {                    // self loop, once per column
        float4 v = __ldg(feat + (size_t)node * 4 + j);
        ax += v.x; ay += v.y; az += v.z; aw += v.w;
    }

    ax += __shfl_xor_sync(0xFFFFFFFFu, ax, 4);
    ay += __shfl_xor_sync(0xFFFFFFFFu, ay, 4);
    az += __shfl_xor_sync(0xFFFFFFFFu, az, 4);
    aw += __shfl_xor_sync(0xFFFFFFFFu, aw, 4);

    float dd = g_dis[node];
    return make_float4(ax * dd, ay * dd, az * dd, aw * dd);
}

// Kernel B: h1 = gather(g_xw); t = relu(h1+b1); g_xw2 = dis * (t @ W2)
__global__ void gather1_kernel(const float* __restrict__ W2,
                               const float* __restrict__ b1, int N) {
    __shared__ float4 ws4[16 * 4];
    __shared__ float  bs[16];
    const int tid = threadIdx.x;
    if (tid < 64) ws4[tid] = ((const float4*)W2)[tid];
    if (tid < 16) bs[tid]  = b1[tid];
    __syncthreads();

    const int lane = tid & 31;
    int node = blockIdx.x * (blockDim.x >> 3) + (tid >> 3);
    bool valid = node < N;
    if (!valid) node = 0;
    const int j = lane & 3;

    float4 h = gather_oct(g_xw, node, lane, g_cnt[node]);

    float tj[4];
    tj[0] = fmaxf(h.x + bs[j * 4 + 0], 0.f);
    tj[1] = fmaxf(h.y + bs[j * 4 + 1], 0.f);
    tj[2] = fmaxf(h.z + bs[j * 4 + 2], 0.f);
    tj[3] = fmaxf(h.w + bs[j * 4 + 3], 0.f);

    float tf[16];
    const int qbase = lane & ~3;
#pragma unroll
    for (int k = 0; k < 16; k++)
        tf[k] = __shfl_sync(0xFFFFFFFFu, tj[k & 3], qbase + (k >> 2));

    float4 acc = make_float4(0.f, 0.f, 0.f, 0.f);
#pragma unroll
    for (int k = 0; k < 16; k++) {
        float4 w = ws4[k * 4 + j];
        acc.x = fmaf(tf[k], w.x, acc.x);
        acc.y = fmaf(tf[k], w.y, acc.y);
        acc.z = fmaf(tf[k], w.z, acc.z);
        acc.w = fmaf(tf[k], w.w, acc.w);
    }

    if (valid && (lane & 4) == 0) {
        float dv = g_dis[node];
        g_xw2[(size_t)node * 4 + j] =
            make_float4(acc.x * dv, acc.y * dv, acc.z * dv, acc.w * dv);
    }
}

// Kernel C: h2 = gather(g_xw2); out = relu(h2+b2) . Wl + bl; reset g_cnt.
__global__ void gather2_kernel(const float* __restrict__ b2,
                               const float* __restrict__ Wl,
                               const float* __restrict__ bl,
                               float* __restrict__ out, int N) {
    __shared__ float bs[16];
    __shared__ float wl[16];
    __shared__ float bl0;
    const int tid = threadIdx.x;
    if (tid < 16) { bs[tid] = b2[tid]; wl[tid] = Wl[tid]; }
    if (tid == 0) bl0 = bl[0];
    __syncthreads();

    const int lane = tid & 31;
    int node = blockIdx.x * (blockDim.x >> 3) + (tid >> 3);
    bool valid = node < N;
    if (!valid) node = 0;
    const int j = lane & 3;

    int cnt = g_cnt[node];
    float4 h = gather_oct(g_xw2, node, lane, cnt);

    float s = fmaxf(h.x + bs[j * 4 + 0], 0.f) * wl[j * 4 + 0]
            + fmaxf(h.y + bs[j * 4 + 1], 0.f) * wl[j * 4 + 1]
            + fmaxf(h.z + bs[j * 4 + 2], 0.f) * wl[j * 4 + 2]
            + fmaxf(h.w + bs[j * 4 + 3], 0.f) * wl[j * 4 + 3];

    s += __shfl_xor_sync(0xFFFFFFFFu, s, 1);
    s += __shfl_xor_sync(0xFFFFFFFFu, s, 2);

    if (valid && (lane & 7) == 0) {
        out[node] = s + bl0;
        g_cnt[node] = 0;             // reset for next launch (after last read)
    }
}

// ---------------------------------------------------------------------------
extern "C" void kernel_launch(void* const* d_in, const int* in_sizes, int n_in,
                              void* d_out, int out_size) {
    const float* x  = (const float*)d_in[0];
    const void*  ei = d_in[1];
    const float* W1 = (const float*)d_in[2];
    const float* b1 = (const float*)d_in[3];
    const float* W2 = (const float*)d_in[4];
    const float* b2 = (const float*)d_in[5];
    const float* Wl = (const float*)d_in[6];
    const float* bl = (const float*)d_in[7];
    float* out = (float*)d_out;

    const int       N = in_sizes[0] / 128;
    const long long E = (long long)in_sizes[1] / 2;

    const int fgBlocks     = (int)(((E + 7) / 8 + FILL_THR - 1) / FILL_THR);
    const int octsPerBlk   = 32;                      // 256 threads
    const int gatherBlocks = (N + octsPerBlk - 1) / octsPerBlk;

    fillgemm_kernel<<<fgBlocks, 256>>>(x, W1, ei, E, N);        // CSR + xw + scale
    gather1_kernel<<<gatherBlocks, 256>>>(W2, b1, N);           // g_xw2
    gather2_kernel<<<gatherBlocks, 256>>>(b2, Wl, bl, out, N);  // out (+ cnt reset)
}

// round 15
// speedup vs baseline: 1.1798x; 1.1798x over previous
#include <cuda_runtime.h>
#include <cuda_bf16.h>

// GCN 2-layer regression on GB300. N=100000 nodes, E=3.2M edges, d_in=128, h=16.
//
// Bucketed-CSR, oct-per-node fp32 gather, warp-specialized fill||gemm overlap
// (the round-10 champion structure):
//   kernel A: warps 0-5 fill CSR buckets (LSU-bound), warps 6-7 compute
//             raw xw = x @ W1 (FMA-bound) -- orthogonal pipes share the SM.
//   kernel B: dis = rsqrt(cnt+1); xw *= dis
//   kernel C: h1 = dis*(self+sum nbr xws1) -> relu+b1 -> @W2 -> *dis -> xws2
//   kernel D: h2 likewise -> relu+b2 -> .Wl+bl -> out  (+ cnt self-reset)
// g_cnt is zeroed in D's epilogue (device globals start zeroed; every run
// leaves them zeroed), so no separate zero pass is needed.

#define MAXN 100000
#define CAP  128            // per-node bucket capacity (Poisson(32) max deg ~65)

__device__ float4 g_xw [MAXN * 4];     // layer-1 features (raw, then dis-scaled)
__device__ float4 g_xw2[MAXN * 4];     // layer-2 dis-scaled features
__device__ float  g_dis[MAXN];         // deg^{-1/2}
__device__ int    g_cnt[MAXN];         // indegree / fill cursors (self-reset)
__device__ int    g_csr[MAXN * CAP];   // bucketed src ids

#define FILL_WARPS 6
#define FILL_THR   (FILL_WARPS * 32)   // 192 fill threads per CTA

// ---------------------------------------------------------------------------
// Kernel A: fused fill (warps 0-5) + raw GEMM1 (warps 6-7).
__global__ void __launch_bounds__(256)
fillgemm_kernel(const float* __restrict__ x, const float* __restrict__ W1,
                const void* __restrict__ ei, long long E, int N) {
    __shared__ float ws[128 * 16];   // W1
    __shared__ float xs[8 * 132];    // x tile for gemm warps (padded)
    __shared__ int   s_is64;

    const int tid = threadIdx.x;
    const int wid = tid >> 5;

    if (tid == 0) {
        // dtype detect: int64 ids < 2^31 -> every odd 32-bit word is 0.
        const int* w = (const int*)ei;
        int az = 1;
        for (int k = 0; k < 64; k++)
            if (w[2 * k + 1] != 0) { az = 0; break; }
        s_is64 = az;
    }
    for (int i = tid; i < 128 * 16; i += 256) ws[i] = W1[i];
    __syncthreads();

    if (wid < FILL_WARPS) {
        // ------------------- fill: 8 edges per thread ---------------------
        const int is64 = s_is64;
        const long long F = (long long)gridDim.x * FILL_THR;
        for (long long c = (long long)blockIdx.x * FILL_THR + tid;
             c * 8 < E; c += F) {
            const long long e0 = c * 8;
            int s[8], d[8];
            int n;
            if (e0 + 8 <= E && (E & 1) == 0) {
                n = 8;
                if (is64) {
                    const longlong2* sp = (const longlong2*)ei;
                    const longlong2* dp = (const longlong2*)((const long long*)ei + E);
#pragma unroll
                    for (int k = 0; k < 4; k++) {
                        longlong2 a = sp[c * 4 + k];
                        s[2 * k] = (int)a.x; s[2 * k + 1] = (int)a.y;
                    }
#pragma unroll
                    for (int k = 0; k < 4; k++) {
                        longlong2 a = dp[c * 4 + k];
                        d[2 * k] = (int)a.x; d[2 * k + 1] = (int)a.y;
                    }
                } else if ((E & 3) == 0) {
                    const int4* sp = (const int4*)ei;
                    const int4* dp = (const int4*)((const int*)ei + E);
#pragma unroll
                    for (int k = 0; k < 2; k++) {
                        int4 a = sp[c * 2 + k];
                        s[4 * k] = a.x; s[4 * k + 1] = a.y;
                        s[4 * k + 2] = a.z; s[4 * k + 3] = a.w;
                    }
#pragma unroll
                    for (int k = 0; k < 2; k++) {
                        int4 a = dp[c * 2 + k];
                        d[4 * k] = a.x; d[4 * k + 1] = a.y;
                        d[4 * k + 2] = a.z; d[4 * k + 3] = a.w;
                    }
                } else {
                    const int* w = (const int*)ei;
#pragma unroll
                    for (int k = 0; k < 8; k++) { s[k] = w[e0 + k]; d[k] = w[E + e0 + k]; }
                }
            } else {
                n = (int)(E - e0 < 8 ? E - e0 : 8);
                for (int k = 0; k < n; k++) {
                    if (is64) {
                        s[k] = (int)((const long long*)ei)[e0 + k];
                        d[k] = (int)((const long long*)ei)[E + e0 + k];
                    } else {
                        s[k] = ((const int*)ei)[e0 + k];
                        d[k] = ((const int*)ei)[E + e0 + k];
                    }
                }
            }
            int pos[8];
#pragma unroll
            for (int k = 0; k < 8; k++)
                if (k < n) pos[k] = atomicAdd(&g_cnt[d[k]], 1);
#pragma unroll
            for (int k = 0; k < 8; k++)
                if (k < n) g_csr[((size_t)d[k] << 7) + pos[k]] = s[k];
        }
    } else {
        // ------------------- gemm: raw xw = x @ W1 ------------------------
        const int gtid = tid - FILL_THR;     // 0..63
        for (int tile = blockIdx.x; tile * 8 < N; tile += gridDim.x) {
            const int base = tile * 8;
            const int rows = min(8, N - base);
            const float4* xg = (const float4*)(x + (size_t)base * 128);
            for (int i = gtid; i < rows * 32; i += 64) {
                float4 v = xg[i];
                int r = i >> 5, cc = (i & 31) * 4;
                float* p = xs + r * 132 + cc;
                p[0] = v.x; p[1] = v.y; p[2] = v.z; p[3] = v.w;
            }
            asm volatile("bar.sync 1, 64;" ::: "memory");

            const int node = gtid >> 3;     // 0..7
            const int j0   = gtid & 7;      // cols j0 and j0+8
            if (node < rows) {
                const float* xr = xs + node * 132;
                float a0 = 0.f, a1 = 0.f;
#pragma unroll
                for (int k = 0; k < 128; k++) {
                    float xv = xr[k];
                    a0 = fmaf(xv, ws[k * 16 + j0],     a0);
                    a1 = fmaf(xv, ws[k * 16 + j0 + 8], a1);
                }
                float* xwp = (float*)g_xw + (size_t)(base + node) * 16;
                xwp[j0]     = a0;           // raw (dis applied by scale_kernel)
                xwp[j0 + 8] = a1;
            }
            asm volatile("bar.sync 1, 64;" ::: "memory");
        }
    }
}

// ---------------------------------------------------------------------------
// Kernel B: dis = rsqrt(cnt+1); g_xw *= dis (grid-stride, one thread/float4).
__global__ void scale_kernel(int N) {
    const int total = N * 4;
    for (int i = blockIdx.x * blockDim.x + threadIdx.x; i < total;
         i += gridDim.x * blockDim.x) {
        int node = i >> 2;
        float dv = rsqrtf((float)(g_cnt[node] + 1));
        float4 v = g_xw[i];
        g_xw[i] = make_float4(v.x * dv, v.y * dv, v.z * dv, v.w * dv);
        if ((i & 3) == 0) g_dis[node] = dv;
    }
}

// ---------------------------------------------------------------------------
// Oct-cooperative neighbor sum. 8 threads per node:
//   column j = lane&3 ; half h = (lane>>2)&1 takes chunks [h*4 + 8i, ..+3].
// One shfl_xor(4) folds the halves. Returns dis*(self+sum) for column j.
__device__ __forceinline__ float4 gather_oct(const float4* __restrict__ feat,
                                             int node, int lane, int cnt) {
    const int j = lane & 3;
    const int h = (lane >> 2) & 1;
    const int beg = node << 7;

    float ax = 0.f, ay = 0.f, az = 0.f, aw = 0.f;

    for (int k = h * 4; k < cnt; k += 8) {
        int4 s4 = *(const int4*)&g_csr[beg + k];   // in-bucket (k 4-aligned < cnt<=128)
        if (k + 0 < cnt) {
            float4 v = __ldg(feat + (size_t)s4.x * 4 + j);
            ax += v.x; ay += v.y; az += v.z; aw += v.w;
        }
        if (k + 1 < cnt) {
            float4 v = __ldg(feat + (size_t)s4.y * 4 + j);
            ax += v.x; ay += v.y; az += v.z; aw += v.w;
        }
        if (k + 2 < cnt) {
            float4 v = __ldg(feat + (size_t)s4.z * 4 + j);
            ax += v.x; ay += v.y; az += v.z; aw += v.w;
        }
        if (k + 3 < cnt) {
            float4 v = __ldg(feat + (size_t)s4.w * 4 + j);
            ax += v.x; ay += v.y; az += v.z; aw += v.w;
        }
    }

    if (h == 0) {                    // self loop, once per column
        float4 v = __ldg(feat + (size_t)node * 4 + j);
        ax += v.x; ay += v.y; az += v.z; aw += v.w;
    }

    ax += __shfl_xor_sync(0xFFFFFFFFu, ax, 4);
    ay += __shfl_xor_sync(0xFFFFFFFFu, ay, 4);
    az += __shfl_xor_sync(0xFFFFFFFFu, az, 4);
    aw += __shfl_xor_sync(0xFFFFFFFFu, aw, 4);

    float dd = g_dis[node];
    return make_float4(ax * dd, ay * dd, az * dd, aw * dd);
}

// Kernel C: h1 = gather(g_xw); t = relu(h1+b1); g_xw2 = dis * (t @ W2)
__global__ void gather1_kernel(const float* __restrict__ W2,
                               const float* __restrict__ b1, int N) {
    __shared__ float4 ws4[16 * 4];
    __shared__ float  bs[16];
    const int tid = threadIdx.x;
    if (tid < 64) ws4[tid] = ((const float4*)W2)[tid];
    if (tid < 16) bs[tid]  = b1[tid];
    __syncthreads();

    const int lane = tid & 31;
    int node = blockIdx.x * (blockDim.x >> 3) + (tid >> 3);
    bool valid = node < N;
    if (!valid) node = 0;
    const int j = lane & 3;

    float4 h = gather_oct(g_xw, node, lane, g_cnt[node]);

    float tj[4];
    tj[0] = fmaxf(h.x + bs[j * 4 + 0], 0.f);
    tj[1] = fmaxf(h.y + bs[j * 4 + 1], 0.f);
    tj[2] = fmaxf(h.z + bs[j * 4 + 2], 0.f);
    tj[3] = fmaxf(h.w + bs[j * 4 + 3], 0.f);

    float tf[16];
    const int qbase = lane & ~3;
#pragma unroll
    for (int k = 0; k < 16; k++)
        tf[k] = __shfl_sync(0xFFFFFFFFu, tj[k & 3], qbase + (k >> 2));

    float4 acc = make_float4(0.f, 0.f, 0.f, 0.f);
#pragma unroll
    for (int k = 0; k < 16; k++) {
        float4 w = ws4[k * 4 + j];
        acc.x = fmaf(tf[k], w.x, acc.x);
        acc.y = fmaf(tf[k], w.y, acc.y);
        acc.z = fmaf(tf[k], w.z, acc.z);
        acc.w = fmaf(tf[k], w.w, acc.w);
    }

    if (valid && (lane & 4) == 0) {
        float dv = g_dis[node];
        g_xw2[(size_t)node * 4 + j] =
            make_float4(acc.x * dv, acc.y * dv, acc.z * dv, acc.w * dv);
    }
}

// Kernel D: h2 = gather(g_xw2); out = relu(h2+b2) . Wl + bl; reset g_cnt.
__global__ void gather2_kernel(const float* __restrict__ b2,
                               const float* __restrict__ Wl,
                               const float* __restrict__ bl,
                               float* __restrict__ out, int N) {
    __shared__ float bs[16];
    __shared__ float wl[16];
    __shared__ float bl0;
    const int tid = threadIdx.x;
    if (tid < 16) { bs[tid] = b2[tid]; wl[tid] = Wl[tid]; }
    if (tid == 0) bl0 = bl[0];
    __syncthreads();

    const int lane = tid & 31;
    int node = blockIdx.x * (blockDim.x >> 3) + (tid >> 3);
    bool valid = node < N;
    if (!valid) node = 0;
    const int j = lane & 3;

    int cnt = g_cnt[node];
    float4 h = gather_oct(g_xw2, node, lane, cnt);

    float s = fmaxf(h.x + bs[j * 4 + 0], 0.f) * wl[j * 4 + 0]
            + fmaxf(h.y + bs[j * 4 + 1], 0.f) * wl[j * 4 + 1]
            + fmaxf(h.z + bs[j * 4 + 2], 0.f) * wl[j * 4 + 2]
            + fmaxf(h.w + bs[j * 4 + 3], 0.f) * wl[j * 4 + 3];

    s += __shfl_xor_sync(0xFFFFFFFFu, s, 1);
    s += __shfl_xor_sync(0xFFFFFFFFu, s, 2);

    if (valid && (lane & 7) == 0) {
        out[node] = s + bl0;
        g_cnt[node] = 0;             // reset for next launch (after last read)
    }
}

// ---------------------------------------------------------------------------
extern "C" void kernel_launch(void* const* d_in, const int* in_sizes, int n_in,
                              void* d_out, int out_size) {
    const float* x  = (const float*)d_in[0];
    const void*  ei = d_in[1];
    const float* W1 = (const float*)d_in[2];
    const float* b1 = (const float*)d_in[3];
    const float* W2 = (const float*)d_in[4];
    const float* b2 = (const float*)d_in[5];
    const float* Wl = (const float*)d_in[6];
    const float* bl = (const float*)d_in[7];
    float* out = (float*)d_out;

    const int       N = in_sizes[0] / 128;
    const long long E = (long long)in_sizes[1] / 2;

    const int fgBlocks     = (int)(((E + 7) / 8 + FILL_THR - 1) / FILL_THR);
    const int scaleBlocks  = (N * 4 + 511) / 512;
    const int octsPerBlk   = 32;                      // 256 threads
    const int gatherBlocks = (N + octsPerBlk - 1) / octsPerBlk;

    fillgemm_kernel<<<fgBlocks, 256>>>(x, W1, ei, E, N);        // CSR + raw xw
    scale_kernel<<<scaleBlocks, 512>>>(N);                      // dis, xw *= dis
    gather1_kernel<<<gatherBlocks, 256>>>(W2, b1, N);           // g_xw2
    gather2_kernel<<<gatherBlocks, 256>>>(b2, Wl, bl, out, N);  // out (+ cnt reset)
}